// round 17
// baseline (speedup 1.0000x reference)
#include <cuda_runtime.h>
#include <math.h>
#include <stdint.h>

#define BATCH 32
#define S 2048
#define BS (BATCH * S)
#define EPSLN 1e-5f
#define L2E 1.4426950408889634f   // log2(e)

#define QKV_KSPLIT 8
#define FC2_KSPLIT 16
#define NCHEB 32
#define NBLK 128

// ---------------- scratch (no allocations allowed) ----------------
__device__ float g_qp[QKV_KSPLIT * BS];
__device__ float g_kp[QKV_KSPLIT * BS];
__device__ float g_vp[QKV_KSPLIT * BS];
__device__ float g_qc[BS];
__device__ float g_kc[BS];
__device__ float g_vc[BS];
__device__ float g_act[BS];
__device__ float g_fcp[FC2_KSPLIT * BS];
__device__ float g_F[BATCH * NCHEB];
__device__ float g_G[BATCH * NCHEB];
__device__ float g_S[BATCH * NCHEB];    // moments S_m = sum_i T_m(u_i)
__device__ float g_rqmn[128], g_rqmx[128], g_rkmn[128], g_rkmx[128];  // 512-elem chunks
__device__ unsigned g_bar_cnt = 0;
__device__ unsigned g_bar_gen = 0;

// ---------------- grid-wide barrier (all NBLK blocks co-resident) ----------------
__device__ __forceinline__ void grid_bar() {
    __syncthreads();
    if (threadIdx.x == 0) {
        volatile unsigned* gen = &g_bar_gen;
        unsigned my = *gen;
        __threadfence();
        unsigned old = atomicAdd(&g_bar_cnt, 1u);
        if (old == NBLK - 1) {
            g_bar_cnt = 0;
            __threadfence();
            atomicAdd(&g_bar_gen, 1u);
        } else {
            while (*gen == my) { }
        }
        __threadfence();
    }
    __syncthreads();
}

__device__ __forceinline__ float ex2f(float x) {
    float y;
    asm("ex2.approx.f32 %0, %1;" : "=f"(y) : "f"(x));
    return y;
}

__device__ __forceinline__ void cp_async16(unsigned dst, const void* src) {
    asm volatile("cp.async.cg.shared.global [%0], [%1], 16;" :: "r"(dst), "l"(src));
}

// split float2 (x = even-k, y = odd-k) into packed bf16x2 hi and lo planes.
__device__ __forceinline__ void bsplit(float2 v, uint32_t& hi, uint32_t& lo) {
    uint32_t h;
    asm("cvt.rn.bf16x2.f32 %0, %1, %2;" : "=r"(h) : "f"(v.y), "f"(v.x));
    float fx = __uint_as_float(h << 16);
    float fy = __uint_as_float(h & 0xffff0000u);
    float lx = v.x - fx, ly = v.y - fy;
    uint32_t l;
    asm("cvt.rn.bf16x2.f32 %0, %1, %2;" : "=r"(l) : "f"(ly), "f"(lx));
    hi = h; lo = l;
}

__device__ __forceinline__ void mma_bf16(float acc[4],
                                         uint32_t a0, uint32_t a1, uint32_t a2, uint32_t a3,
                                         uint32_t b0, uint32_t b1) {
    asm volatile("mma.sync.aligned.m16n8k16.row.col.f32.bf16.bf16.f32 "
                 "{%0,%1,%2,%3}, {%4,%5,%6,%7}, {%8,%9}, {%0,%1,%2,%3};"
                 : "+f"(acc[0]), "+f"(acc[1]), "+f"(acc[2]), "+f"(acc[3])
                 : "r"(a0), "r"(a1), "r"(a2), "r"(a3), "r"(b0), "r"(b1));
}

// warp-parallel DCT-II: lane m returns a_m; cos via 3-term recurrence, src by shuffle.
__device__ __forceinline__ float warp_dct(float srclane, int lane) {
    const float m = (float)lane;
    float cpp = cospif(0.5f * m * (1.0f / NCHEB));
    float cp  = cospif(1.5f * m * (1.0f / NCHEB));
    const float r = 2.0f * cospif(m * (1.0f / NCHEB));
    float s = __shfl_sync(0xffffffffu, srclane, 0) * cpp
            + __shfl_sync(0xffffffffu, srclane, 1) * cp;
    #pragma unroll
    for (int n = 2; n < NCHEB; n++) {
        float cn = fmaf(r, cp, -cpp);
        s = fmaf(__shfl_sync(0xffffffffu, srclane, n), cn, s);
        cpp = cp; cp = cn;
    }
    return s * ((lane == 0) ? (1.0f / NCHEB) : (2.0f / NCHEB));
}

// batch-level range + shift M; identical fp sequence at every call site (4 chunks/batch)
__device__ __forceinline__ void batch_range(int b, float& c, float& h, float& M) {
    float qmn = 3.0e38f, qmx = -3.0e38f, kmn = 3.0e38f, kmx = -3.0e38f;
    #pragma unroll
    for (int j = 0; j < 4; j++) {
        qmn = fminf(qmn, g_rqmn[b * 4 + j]);
        qmx = fmaxf(qmx, g_rqmx[b * 4 + j]);
        kmn = fminf(kmn, g_rkmn[b * 4 + j]);
        kmx = fmaxf(kmx, g_rkmx[b * 4 + j]);
    }
    c = 0.5f * (qmn + qmx);
    h = fmaxf(0.5f * (qmx - qmn), 1e-30f);
    M = fmaxf(fmaxf(qmn * kmn, qmn * kmx), fmaxf(qmx * kmn, qmx * kmx));
}

// ---------------- bf16 tensor-core GEMM, 3-stage cp.async pipeline ----------------
// Dynamic smem: sW = float[3][5120] (61440B), sXh/sXl at +61440 (4096B). Total 65536B.
#define WSTRIDE 40
#define WSTAGE (128 * WSTRIDE)

template <int NCHUNK>
__device__ __forceinline__ void gemm_bf16(char* smem,
                                          const float* __restrict__ X,
                                          const float* __restrict__ W,
                                          float* __restrict__ out,
                                          int c0, int kb0)
{
    float* sW = (float*)smem;                       // [3][WSTAGE]
    uint32_t* sXh = (uint32_t*)(smem + 61440);      // [512]
    uint32_t* sXl = sXh + 512;                      // [512]

    const int tid = threadIdx.x;
    const int lane = tid & 31, w = tid >> 5;

    float acc[4][4];
    #pragma unroll
    for (int g = 0; g < 4; g++)
        #pragma unroll
        for (int j = 0; j < 4; j++) acc[g][j] = 0.f;

    const unsigned swbase = (unsigned)__cvta_generic_to_shared(smem);
    const int wrow = tid >> 3, wq = tid & 7;

    const int sg   = tid >> 6;
    const int sln  = (tid >> 1) & 31;
    const int sbrg = tid & 1;
    const int sn   = sg * 8 + (sln >> 2);
    const int skk  = sbrg * 8 + 2 * (sln & 3);
    const float* xp = X + (size_t)sn * S + kb0 + skk;

    // prologue: issue chunks 0 and 1
    #pragma unroll
    for (int i = 0; i < 4; i++) {
        int r = wrow + i * 32;
        cp_async16(swbase + (unsigned)((r * WSTRIDE + wq * 4) * 4),
                   W + (size_t)(c0 + r) * S + kb0 + wq * 4);
    }
    asm volatile("cp.async.commit_group;");
    if (NCHUNK > 1) {
        #pragma unroll
        for (int i = 0; i < 4; i++) {
            int r = wrow + i * 32;
            cp_async16(swbase + (unsigned)(20480 + (r * WSTRIDE + wq * 4) * 4),
                       W + (size_t)(c0 + r) * S + kb0 + 32 + wq * 4);
        }
        asm volatile("cp.async.commit_group;");
    }
    float2 xr0 = *(const float2*)(xp);
    float2 xr1 = *(const float2*)(xp + 16);

    for (int ch = 0; ch < NCHUNK; ch++) {
        if (ch + 1 < NCHUNK) asm volatile("cp.async.wait_group 1;");
        else                 asm volatile("cp.async.wait_group 0;");
        __syncthreads();   // chunk ch landed; all warps past chunk ch-1 compute

        if (ch + 2 < NCHUNK) {
            const int kb = kb0 + (ch + 2) * 32;
            const unsigned stoff = (unsigned)(((ch + 2) % 3) * 20480);
            #pragma unroll
            for (int i = 0; i < 4; i++) {
                int r = wrow + i * 32;
                cp_async16(swbase + stoff + (unsigned)((r * WSTRIDE + wq * 4) * 4),
                           W + (size_t)(c0 + r) * S + kb + wq * 4);
            }
            asm volatile("cp.async.commit_group;");
        }

        {
            uint32_t h0, l0, h1, l1;
            bsplit(xr0, h0, l0);
            bsplit(xr1, h1, l1);
            sXh[tid] = h0;       sXl[tid] = l0;
            sXh[tid + 256] = h1; sXl[tid + 256] = l1;
        }
        if (ch + 1 < NCHUNK) {
            xr0 = *(const float2*)(xp + (ch + 1) * 32);
            xr1 = *(const float2*)(xp + (ch + 1) * 32 + 16);
        }
        __syncthreads();

        const float* ws = sW + (ch % 3) * WSTAGE;
        const int rb = w * 16 + (lane >> 2);
        const int kc = 2 * (lane & 3);

        #pragma unroll
        for (int s = 0; s < 2; s++) {
            float2 ra0 = *(const float2*)&ws[rb * WSTRIDE + s * 16 + kc];
            float2 ra2 = *(const float2*)&ws[rb * WSTRIDE + s * 16 + 8 + kc];
            float2 ra1 = *(const float2*)&ws[(rb + 8) * WSTRIDE + s * 16 + kc];
            float2 ra3 = *(const float2*)&ws[(rb + 8) * WSTRIDE + s * 16 + 8 + kc];
            uint32_t A0h, A0l, A1h, A1l, A2h, A2l, A3h, A3l;
            bsplit(ra0, A0h, A0l);
            bsplit(ra1, A1h, A1l);
            bsplit(ra2, A2h, A2l);
            bsplit(ra3, A3h, A3l);

            #pragma unroll
            for (int g = 0; g < 4; g++) {
                const int base = ((s * 4 + g) << 6) + (lane << 1);
                uint2 bh = *(const uint2*)&sXh[base];
                uint2 bl = *(const uint2*)&sXl[base];
                mma_bf16(acc[g], A0h, A1h, A2h, A3h, bh.x, bh.y);
                mma_bf16(acc[g], A0h, A1h, A2h, A3h, bl.x, bl.y);
                mma_bf16(acc[g], A0l, A1l, A2l, A3l, bh.x, bh.y);
            }
        }
    }

    const int c = c0 + w * 16 + (lane >> 2);
    #pragma unroll
    for (int g = 0; g < 4; g++) {
        const int b = g * 8 + 2 * (lane & 3);
        out[(size_t)b * S + c]           = acc[g][0];
        out[(size_t)(b + 1) * S + c]     = acc[g][1];
        out[(size_t)b * S + c + 8]       = acc[g][2];
        out[(size_t)(b + 1) * S + c + 8] = acc[g][3];
    }
}

// ---------------- phase: combine qkv partials (512-elem chunk per block) --------------
__device__ void do_combine(int B) {
    __shared__ float r0[8], r1[8], r2[8], r3[8];
    const int tid = threadIdx.x;
    const int e0 = B * 512 + tid * 2;

    float2 q = make_float2(0.f, 0.f), k = q, v = q;
    #pragma unroll
    for (int p = 0; p < QKV_KSPLIT; p++) {
        float2 a = *(const float2*)&g_qp[(size_t)p * BS + e0];
        float2 bq = *(const float2*)&g_kp[(size_t)p * BS + e0];
        float2 c = *(const float2*)&g_vp[(size_t)p * BS + e0];
        q.x += a.x; q.y += a.y;
        k.x += bq.x; k.y += bq.y;
        v.x += c.x; v.y += c.y;
    }
    *(float2*)&g_qc[e0] = q;
    *(float2*)&g_kc[e0] = k;
    *(float2*)&g_vc[e0] = v;

    float qmn = fminf(q.x, q.y), qmx = fmaxf(q.x, q.y);
    float kmn = fminf(k.x, k.y), kmx = fmaxf(k.x, k.y);
    #pragma unroll
    for (int off = 16; off > 0; off >>= 1) {
        qmn = fminf(qmn, __shfl_xor_sync(0xffffffffu, qmn, off));
        qmx = fmaxf(qmx, __shfl_xor_sync(0xffffffffu, qmx, off));
        kmn = fminf(kmn, __shfl_xor_sync(0xffffffffu, kmn, off));
        kmx = fmaxf(kmx, __shfl_xor_sync(0xffffffffu, kmx, off));
    }
    const int lane = tid & 31, wid = tid >> 5;
    if (lane == 0) { r0[wid] = qmn; r1[wid] = qmx; r2[wid] = kmn; r3[wid] = kmx; }
    __syncthreads();
    if (tid == 0) {
        float a = r0[0], b = r1[0], c = r2[0], d = r3[0];
        #pragma unroll
        for (int w = 1; w < 8; w++) {
            a = fminf(a, r0[w]); b = fmaxf(b, r1[w]);
            c = fminf(c, r2[w]); d = fmaxf(d, r3[w]);
        }
        g_rqmn[B] = a; g_rqmx[B] = b; g_rkmn[B] = c; g_rkmx[B] = d;
    }
}

// ---------------- phase: Chebyshev node evaluation (item B: batch B>>2, group B&3) ----
__device__ void do_nodes(char* smem, int B) {
    float* sk = (float*)smem;             // [S]
    float* sv = (float*)(smem + 8192);    // [S]
    const int b = B >> 2, grp = B & 3;
    const int tid = threadIdx.x;
    const int lane = tid & 31, w = tid >> 5;

    for (int idx = tid; idx < S; idx += 256) {
        sk[idx] = g_kc[b * S + idx];
        sv[idx] = g_vc[b * S + idx];
    }
    __syncthreads();

    float c, h, M;
    batch_range(b, c, h, M);
    const float Ml2e = M * L2E;

    const int n = grp * 8 + w;
    const float t = fmaf(h, cospif((n + 0.5f) * (1.0f / NCHEB)), c);
    const float tl = t * L2E;
    float F = 0.f, G = 0.f;
    #pragma unroll 4
    for (int j = lane; j < S; j += 32) {
        float e = ex2f(fmaf(tl, sk[j], -Ml2e));
        F = fmaf(e, sv[j], F);
        G += e;
    }
    #pragma unroll
    for (int off = 16; off > 0; off >>= 1) {
        F += __shfl_xor_sync(0xffffffffu, F, off);
        G += __shfl_xor_sync(0xffffffffu, G, off);
    }
    if (lane == 0) {
        g_F[b * NCHEB + n] = F;
        g_G[b * NCHEB + n] = G;
    }
}

// ---------------- phase: q-moments for batch b ----------------
__device__ void do_moments(int b) {
    __shared__ float sS[NCHEB][9];
    const int tid = threadIdx.x;
    const int lane = tid & 31, w = tid >> 5;

    float c, h, M;
    batch_range(b, c, h, M);
    const float hinv = 1.0f / h;

    float acc[NCHEB];
    #pragma unroll
    for (int m = 0; m < NCHEB; m++) acc[m] = 0.f;

    #pragma unroll
    for (int jj = 0; jj < 8; jj++) {
        const int i = tid + jj * 256;
        float u = fminf(1.f, fmaxf(-1.f, (g_qc[b * S + i] - c) * hinv));
        float t0 = 1.f, t1 = u;
        acc[0] += t0;
        acc[1] += t1;
        #pragma unroll
        for (int m = 2; m < NCHEB; m++) {
            float tm = fmaf(u + u, t1, -t0);
            acc[m] += tm;
            t0 = t1; t1 = tm;
        }
    }
    #pragma unroll
    for (int m = 0; m < NCHEB; m++) {
        float s = acc[m];
        #pragma unroll
        for (int off = 16; off > 0; off >>= 1)
            s += __shfl_xor_sync(0xffffffffu, s, off);
        if (lane == 0) sS[m][w] = s;
    }
    __syncthreads();
    if (tid < NCHEB) {
        float s = 0.f;
        #pragma unroll
        for (int ww = 0; ww < 8; ww++) s += sS[tid][ww];
        g_S[b * NCHEB + tid] = s;
    }
}

// ---------------- phase: warp-DCT + Z + Clenshaw + activation (item B) ----------------
__device__ void do_evalact(int B, const float* __restrict__ p2) {
    __shared__ float saF[NCHEB];
    __shared__ float sZ, sPs0, sPs1, sPs2;

    const int b = B >> 2, y = B & 3;
    const int tid = threadIdx.x;
    const int lane = tid & 31, wid = tid >> 5;

    if (tid == 96) {
        float p[5];
        #pragma unroll
        for (int t = 0; t < 5; t++) p[t] = p2[t];
        float pm = p[0];
        #pragma unroll
        for (int t = 1; t < 5; t++) pm = fmaxf(pm, p[t]);
        float pe[5], psum = 0.f;
        #pragma unroll
        for (int t = 0; t < 5; t++) { pe[t] = ex2f((p[t] - pm) * L2E); psum += pe[t]; }
        float inv = __fdividef(1.0f, psum);
        sPs0 = pe[0] * inv; sPs1 = pe[1] * inv; sPs2 = pe[2] * inv;
    }
    if (wid == 0) {
        saF[lane] = warp_dct(g_F[b * NCHEB + lane], lane);
    } else if (wid == 1) {
        float ag = warp_dct(g_G[b * NCHEB + lane], lane);
        float z = ag * g_S[b * NCHEB + lane];
        #pragma unroll
        for (int off = 16; off > 0; off >>= 1)
            z += __shfl_xor_sync(0xffffffffu, z, off);
        if (lane == 0) sZ = z;
    }
    __syncthreads();

    float c, h, M;
    batch_range(b, c, h, M);
    const float hinv = 1.0f / h;
    const float Z = sZ;
    const float ps0 = sPs0, ps1 = sPs1, ps2 = sPs2;

    const int i0 = y * 512 + tid;
    float ua, ub;
    {
        float ta = g_qc[b * S + i0];
        float tb = g_qc[b * S + i0 + 256];
        ua = fminf(1.f, fmaxf(-1.f, (ta - c) * hinv));
        ub = fminf(1.f, fmaxf(-1.f, (tb - c) * hinv));
    }
    const float ua2 = ua + ua, ub2 = ub + ub;
    float fa1 = 0.f, fa2 = 0.f, fb1 = 0.f, fb2 = 0.f;
    #pragma unroll
    for (int m = NCHEB - 1; m >= 1; m--) {
        const float am = saF[m];
        float na = fmaf(ua2, fa1, am - fa2); fa2 = fa1; fa1 = na;
        float nb = fmaf(ub2, fb1, am - fb2); fb2 = fb1; fb1 = nb;
    }
    const float a0 = saF[0];
    const float Fa = fmaf(ua, fa1, a0 - fa2);
    const float Fb = fmaf(ub, fb1, a0 - fb2);

    {
        const float val = __fdividef(Fa, Z);
        const float sig = __fdividef(1.0f, 1.0f + ex2f(-val * L2E));
        g_act[b * S + i0] = sig * val * ps0 + __sinf(val) * ps1 + val * ps2;
    }
    {
        const float val = __fdividef(Fb, Z);
        const float sig = __fdividef(1.0f, 1.0f + ex2f(-val * L2E));
        g_act[b * S + i0 + 256] = sig * val * ps0 + __sinf(val) * ps1 + val * ps2;
    }
}

// ---------------- phase: combine fc2 partials + bias + LayerNorm (batch b) -----------
__device__ void do_ln(char* smem, int b,
                      const float* __restrict__ bias,
                      const float* __restrict__ g2,
                      const float* __restrict__ b2,
                      float* __restrict__ out) {
    float* sRow = (float*)smem;   // [S]
    __shared__ float rsum[8], rsq[8];
    __shared__ float sMu, sRstd;

    const int tid = threadIdx.x;
    const int lane = tid & 31, wid = tid >> 5;

    float s = 0.f, s2 = 0.f;
    #pragma unroll
    for (int it = 0; it < 8; it++) {
        int idx = tid + it * 256;
        float v = bias[idx];
        #pragma unroll
        for (int p = 0; p < FC2_KSPLIT; p++)
            v += g_fcp[(size_t)p * BS + b * S + idx];
        sRow[idx] = v;
        s += v;
        s2 = fmaf(v, v, s2);
    }
    #pragma unroll
    for (int off = 16; off > 0; off >>= 1) {
        s  += __shfl_xor_sync(0xffffffffu, s,  off);
        s2 += __shfl_xor_sync(0xffffffffu, s2, off);
    }
    if (lane == 0) { rsum[wid] = s; rsq[wid] = s2; }
    __syncthreads();
    if (tid == 0) {
        float ts = 0.f, ts2 = 0.f;
        #pragma unroll
        for (int w = 0; w < 8; w++) { ts += rsum[w]; ts2 += rsq[w]; }
        float mu = ts * (1.0f / S);
        float var = ts2 * (1.0f / S) - mu * mu;
        sMu = mu;
        sRstd = rsqrtf(var + EPSLN);
    }
    __syncthreads();

    const float mu = sMu, rstd = sRstd;
    #pragma unroll
    for (int it = 0; it < 8; it++) {
        int idx = tid + it * 256;
        out[b * S + idx] = (sRow[idx] - mu) * rstd * g2[idx] + b2[idx];
    }
}

// ---------------- THE kernel: everything, with grid barriers ----------------
__global__ void __launch_bounds__(256) mega_kernel(
    const float* __restrict__ x,
    const float* __restrict__ Wq,
    const float* __restrict__ Wk,
    const float* __restrict__ Wv,
    const float* __restrict__ p2,
    const float* __restrict__ Wfc2,
    const float* __restrict__ bfc2,
    const float* __restrict__ g2,
    const float* __restrict__ b2,
    float* __restrict__ out)
{
    extern __shared__ char smem[];
    const int B = blockIdx.x;

    // phase 1: QKV GEMM — 384 tiles, 3 per block
    #pragma unroll 1
    for (int t = B; t < 384; t += NBLK) {
        const int z = t / 128, rem = t % 128;
        const int ct = rem & 15, ks = rem >> 4;
        const float* W = (z == 0) ? Wq : (z == 1 ? Wk : Wv);
        float* o = ((z == 0) ? g_qp : (z == 1 ? g_kp : g_vp)) + (size_t)ks * BS;
        gemm_bf16<(S / QKV_KSPLIT) / 32>(smem, x, W, o, ct * 128, ks * (S / QKV_KSPLIT));
        __syncthreads();
    }
    grid_bar();

    // phase 2: combine partials + range chunks
    do_combine(B);
    grid_bar();

    // phase 3: Chebyshev nodes (all blocks) + moments (blocks 96..127)
    do_nodes(smem, B);
    if (B >= 96) { __syncthreads(); do_moments(B - 96); }
    grid_bar();

    // phase 4: DCT + Z + Clenshaw + activation
    do_evalact(B, p2);
    grid_bar();

    // phase 5: fc2 GEMM — 256 tiles, 2 per block
    #pragma unroll 1
    for (int t = B; t < 256; t += NBLK) {
        const int ct = t & 15, ks = t >> 4;
        gemm_bf16<(S / FC2_KSPLIT) / 32>(smem, g_act, Wfc2, g_fcp + (size_t)ks * BS,
                                         ct * 128, ks * (S / FC2_KSPLIT));
        __syncthreads();
    }
    grid_bar();

    // phase 6: layernorm (blocks 0..31)
    if (B < BATCH)
        do_ln(smem, B, bfc2, g2, b2, out);
}

// ---------------- launch ----------------
extern "C" void kernel_launch(void* const* d_in, const int* in_sizes, int n_in,
                              void* d_out, int out_size) {
    const float* x    = (const float*)d_in[0];
    const float* Wq   = (const float*)d_in[1];
    const float* Wk   = (const float*)d_in[2];
    const float* Wv   = (const float*)d_in[3];
    const float* p2   = (const float*)d_in[4];
    const float* Wfc2 = (const float*)d_in[5];
    const float* bfc2 = (const float*)d_in[6];
    const float* g2   = (const float*)d_in[7];
    const float* b2   = (const float*)d_in[8];
    float* out = (float*)d_out;

    static int attr_set = 0;
    if (!attr_set) {
        cudaFuncSetAttribute(mega_kernel, cudaFuncAttributeMaxDynamicSharedMemorySize, 65536);
        attr_set = 1;
    }
    mega_kernel<<<NBLK, 256, 65536>>>(x, Wq, Wk, Wv, p2, Wfc2, bfc2, g2, b2, out);
}